// round 3
// baseline (speedup 1.0000x reference)
#include <cuda_runtime.h>
#include <cuda_bf16.h>

// x: (128,1,32768) fp32, 17 fixed filters baked as constants, out: (128,17,32768) = relu(conv same), PAD_LO=47.
// Filters 0..5 alternating even-neg K={2,4,8,16,32,64}; 6..11 odd-neg (negation); 12..16 piecewise-quadratic
// bumps len 1.5K, K=4..64.  Quad filter = [-B, 2B, -B] with bump B of len K/2 -> z = B*x shared per block.

#define NB    128
#define LSEQ  32768
#define NFILT 17
#define TILE  1024
#define NTHR  256
#define NSV   1119
#define NSX   1120

__device__ __forceinline__ float triWeightAbs(int t, int c) {
    // t=0..4 <-> K=4,8,16,32,64 quad filter weight at absolute tap c in [0,96)
    const int Ks[5] = {4, 8, 16, 32, 64};
    int K = Ks[t];
    int Lf = K + K / 2;
    int o = 47 - (Lf - 1) / 2;
    int j = c - o;
    if (j < 0 || j >= Lf) return 0.0f;
    int q = K / 4, half = K / 2;
    int s = j / half;
    int u = j - s * half;
    int num = (u < q) ? (u + 1) : (half - u);
    float b = (float)num / (float)q;
    float w = b * b;
    return (s == 1) ? 2.0f * w : -w;
}

__device__ __forceinline__ float bumpW(int half, int j) {
    // bump B(j), j in [0, half): rising ((j+1)/q)^2 then mirrored fall, q=half/2 (power of two -> exact)
    int q = half / 2;
    int num = (j < q) ? (j + 1) : (half - j);
    float b = (float)num / (float)q;
    return b * b;
}

template<int HALF, int OF, int GK>
__device__ __forceinline__ void computeZ(const float* __restrict__ xs,
                                         float* __restrict__ z, int tid) {
    #pragma unroll
    for (int pass = 0; pass < 2; ++pass) {
        int g = tid + pass * NTHR;
        if (pass == 1 && tid >= GK - NTHR) break;
        const int s = 4 * g;
        const int a = s + OF;                     // OF multiple of 4 -> aligned
        float a0 = 0.f, a1 = 0.f, a2 = 0.f, a3 = 0.f;
        float4 cur = *(const float4*)(xs + a);
        #pragma unroll
        for (int m = 0; m < HALF / 4; ++m) {
            float4 nxt = *(const float4*)(xs + a + 4 * m + 4);
            float win[8] = {cur.x, cur.y, cur.z, cur.w, nxt.x, nxt.y, nxt.z, nxt.w};
            #pragma unroll
            for (int d = 0; d < 4; ++d) {
                const float w = bumpW(HALF, 4 * m + d);
                a0 = fmaf(w, win[d], a0);
                a1 = fmaf(w, win[d + 1], a1);
                a2 = fmaf(w, win[d + 2], a2);
                a3 = fmaf(w, win[d + 3], a3);
            }
            cur = nxt;
        }
        *(float4*)(z + s) = make_float4(a0, a1, a2, a3);
    }
}

__global__ __launch_bounds__(NTHR, 6)
void Hybrid_block_64175401337035_kernel(const float* __restrict__ x,
                                        float* __restrict__ y) {
    __shared__ __align__(16) float xs[NSX];
    __shared__ __align__(16) float E[NSX];       // E[p] = (-1)^p * alternating prefix
    __shared__ __align__(16) float z16[1040];    // z for K=16 (half=8,  o_f=36), idx = a-o_f
    __shared__ __align__(16) float z32[1056];    // K=32 (half=16, o_f=24)
    __shared__ __align__(16) float z64[1088];    // K=64 (half=32, o_f=0)
    __shared__ float warpAgg[8];

    const int tid = threadIdx.x;
    const int n = blockIdx.y;
    const int tileStart = blockIdx.x * TILE;
    const float* xg = x + (size_t)n * LSEQ;

    // ---- load input tile (zero-padded at sequence edges) ----
    for (int q = tid; q < NSX; q += NTHR) {
        int g = tileStart - 47 + q;
        xs[q] = (q < NSV && g >= 0 && g < LSEQ) ? xg[g] : 0.0f;
    }
    __syncthreads();

    // ---- block scan of (-1)^q xs[q], 5 elems/thread ----
    float loc[5];
    float run = 0.0f;
    const int qb = tid * 5;
    #pragma unroll
    for (int j = 0; j < 5; ++j) {
        int q = qb + j;
        float v = 0.0f;
        if (q < NSV) { v = xs[q]; if (q & 1) v = -v; }
        run += v;
        loc[j] = run;
    }
    const unsigned lane = tid & 31;
    const unsigned wid = tid >> 5;
    float inc = run;
    #pragma unroll
    for (int o = 1; o < 32; o <<= 1) {
        float nb = __shfl_up_sync(0xffffffffu, inc, o);
        if (lane >= (unsigned)o) inc += nb;
    }
    if (lane == 31) warpAgg[wid] = inc;
    __syncthreads();
    if (tid < 8) {
        float wv = warpAgg[tid];
        #pragma unroll
        for (int o = 1; o < 8; o <<= 1) {
            float nb = __shfl_up_sync(0xffu, wv, o);
            if (tid >= o) wv += nb;
        }
        warpAgg[tid] = wv;
    }
    __syncthreads();
    float pre = inc - run;
    if (wid > 0) pre += warpAgg[wid - 1];
    if (tid == 0) E[0] = 0.0f;
    #pragma unroll
    for (int j = 0; j < 5; ++j) {
        int q = qb + j;
        if (q < NSV) {
            float v = pre + loc[j];
            E[q + 1] = (q & 1) ? v : -v;
        }
    }
    __syncthreads();

    const int xl0 = tid * 4;
    const int i0 = tileStart + xl0;
    float* ybase = y + (size_t)n * NFILT * LSEQ + i0;

    // ---- 12 alternating filters via aligned E windows ----
    {
        const float4 e16 = *(const float4*)(E + xl0 + 16);
        const float4 e32 = *(const float4*)(E + xl0 + 32);
        const float4 e40 = *(const float4*)(E + xl0 + 40);
        const float4 e44 = *(const float4*)(E + xl0 + 44);
        const float4 e48 = *(const float4*)(E + xl0 + 48);
        const float4 e52 = *(const float4*)(E + xl0 + 52);
        const float4 e56 = *(const float4*)(E + xl0 + 56);
        const float4 e64 = *(const float4*)(E + xl0 + 64);
        const float4 e80 = *(const float4*)(E + xl0 + 80);

        float w0[4], w1[4];
        #define EMIT(kkidx)                                                          \
        {                                                                            \
            float4 ye, yo;                                                           \
            ye.x = fmaxf(w0[0] - w1[0], 0.0f); yo.x = fmaxf(w1[0] - w0[0], 0.0f);    \
            ye.y = fmaxf(w0[1] - w1[1], 0.0f); yo.y = fmaxf(w1[1] - w0[1], 0.0f);    \
            ye.z = fmaxf(w0[2] - w1[2], 0.0f); yo.z = fmaxf(w1[2] - w0[2], 0.0f);    \
            ye.w = fmaxf(w0[3] - w1[3], 0.0f); yo.w = fmaxf(w1[3] - w0[3], 0.0f);    \
            *(float4*)(ybase + (size_t)(kkidx) * LSEQ) = ye;                         \
            *(float4*)(ybase + (size_t)(6 + (kkidx)) * LSEQ) = yo;                   \
        }
        w0[0]=e44.w; w0[1]=e48.x; w0[2]=e48.y; w0[3]=e48.z;           // K=2 @47
        w1[0]=e48.y; w1[1]=e48.z; w1[2]=e48.w; w1[3]=e52.x;
        EMIT(0)
        w0[0]=e44.z; w0[1]=e44.w; w0[2]=e48.x; w0[3]=e48.y;           // K=4 @46
        w1[0]=e48.z; w1[1]=e48.w; w1[2]=e52.x; w1[3]=e52.y;
        EMIT(1)
        w0[0]=e44.x; w0[1]=e44.y; w0[2]=e44.z; w0[3]=e44.w;           // K=8 @44
        w1[0]=e52.x; w1[1]=e52.y; w1[2]=e52.z; w1[3]=e52.w;
        EMIT(2)
        w0[0]=e40.x; w0[1]=e40.y; w0[2]=e40.z; w0[3]=e40.w;           // K=16 @40
        w1[0]=e56.x; w1[1]=e56.y; w1[2]=e56.z; w1[3]=e56.w;
        EMIT(3)
        w0[0]=e32.x; w0[1]=e32.y; w0[2]=e32.z; w0[3]=e32.w;           // K=32 @32
        w1[0]=e64.x; w1[1]=e64.y; w1[2]=e64.z; w1[3]=e64.w;
        EMIT(4)
        w0[0]=e16.x; w0[1]=e16.y; w0[2]=e16.z; w0[3]=e16.w;           // K=64 @16
        w1[0]=e80.x; w1[1]=e80.y; w1[2]=e80.z; w1[3]=e80.w;
        EMIT(5)
        #undef EMIT
    }

    // ---- quad K=4,8 direct (18 taps over xs[xl0+42 .. xl0+56]) ----
    {
        float acc[2][4];
        #pragma unroll
        for (int t = 0; t < 2; ++t)
            #pragma unroll
            for (int pp = 0; pp < 4; ++pp) acc[t][pp] = 0.0f;

        float4 cur = *(const float4*)(xs + xl0 + 40);
        #pragma unroll
        for (int m = 0; m < 4; ++m) {
            float4 nxt = *(const float4*)(xs + xl0 + 44 + 4 * m);
            float win[8] = {cur.x, cur.y, cur.z, cur.w, nxt.x, nxt.y, nxt.z, nxt.w};
            #pragma unroll
            for (int d = 0; d < 4; ++d) {
                const int c = 40 + 4 * m + d;
                #pragma unroll
                for (int t = 0; t < 2; ++t) {
                    const float w = triWeightAbs(t, c);
                    if (w != 0.0f) {
                        #pragma unroll
                        for (int pp = 0; pp < 4; ++pp)
                            acc[t][pp] = fmaf(w, win[d + pp], acc[t][pp]);
                    }
                }
            }
            cur = nxt;
        }
        #pragma unroll
        for (int t = 0; t < 2; ++t) {
            float4 v;
            v.x = fmaxf(acc[t][0], 0.0f);
            v.y = fmaxf(acc[t][1], 0.0f);
            v.z = fmaxf(acc[t][2], 0.0f);
            v.w = fmaxf(acc[t][3], 0.0f);
            *(float4*)(ybase + (size_t)(12 + t) * LSEQ) = v;
        }
    }

    // ---- phase A: bump sequences z_K = B_K * x into smem ----
    computeZ< 8, 36, 260>(xs, z16, tid);
    computeZ<16, 24, 264>(xs, z32, tid);
    computeZ<32,  0, 272>(xs, z64, tid);
    __syncthreads();

    // ---- phase B: y = relu(-z(i) + 2 z(i+half) - z(i+K)) for K=16,32,64 ----
    {
        #define QEMIT(ZARR, HALF, FIDX)                                              \
        {                                                                            \
            const float4 z0 = *(const float4*)((ZARR) + xl0);                        \
            const float4 zm = *(const float4*)((ZARR) + xl0 + (HALF));               \
            const float4 z2 = *(const float4*)((ZARR) + xl0 + 2 * (HALF));           \
            float4 v;                                                                \
            v.x = fmaxf(fmaf(2.0f, zm.x, -(z0.x + z2.x)), 0.0f);                     \
            v.y = fmaxf(fmaf(2.0f, zm.y, -(z0.y + z2.y)), 0.0f);                     \
            v.z = fmaxf(fmaf(2.0f, zm.z, -(z0.z + z2.z)), 0.0f);                     \
            v.w = fmaxf(fmaf(2.0f, zm.w, -(z0.w + z2.w)), 0.0f);                     \
            *(float4*)(ybase + (size_t)(FIDX) * LSEQ) = v;                           \
        }
        QEMIT(z16, 8, 14)
        QEMIT(z32, 16, 15)
        QEMIT(z64, 32, 16)
        #undef QEMIT
    }
}

extern "C" void kernel_launch(void* const* d_in, const int* in_sizes, int n_in,
                              void* d_out, int out_size) {
    const float* x = (const float*)d_in[0];
    float* y = (float*)d_out;
    dim3 grid(LSEQ / TILE, NB);
    Hybrid_block_64175401337035_kernel<<<grid, NTHR>>>(x, y);
}

// round 4
// speedup vs baseline: 1.0127x; 1.0127x over previous
#include <cuda_runtime.h>
#include <cuda_bf16.h>

// x: (128,1,32768) fp32, W: 17 fixed filters (baked as constants), out: (128,17,32768) = relu(conv same)
// PAD_LO=47. Filters 0..5 alternating even-negative K={2,4,8,16,32,64}; 6..11 odd-negative (negation);
// 12..16 piecewise-quadratic bumps, len 1.5K for K=4..64.
//
// R4 change vs best (R2): identical compute; launch reserves 38KB of (unused) dynamic smem so
// occupancy is capped at 4 blocks/SM -> 592 concurrent blocks -> grid 4096 = 6.92 waves (98.8%
// schedule efficiency) instead of 4.61 waves at 6 blocks/SM (92.2%).

#define NB    128
#define LSEQ  32768
#define NFILT 17
#define TILE  1024
#define NTHR  256
#define NSV   1119          // valid xs elements = TILE + 95
#define NSX   1120
#define DYN_PAD_BYTES 38912 // occupancy shaping: (8992 static + 38912) * 5 > 228KB, * 4 fits

__device__ __forceinline__ float triWeightAbs(int t, int c) {
    // weight of quad filter t (t=0..4 <-> K=4,8,16,32,64) at absolute tap c (0..95); 0 outside support
    const int Ks[5] = {4, 8, 16, 32, 64};
    int K = Ks[t];
    int Lf = K + K / 2;
    int o = 47 - (Lf - 1) / 2;
    int j = c - o;
    if (j < 0 || j >= Lf) return 0.0f;
    int q = K / 4, half = K / 2;
    int s = j / half;
    int u = j - s * half;
    int num = (u < q) ? (u + 1) : (half - u);
    float b = (float)num / (float)q;        // exact: power-of-two denominator
    float w = b * b;
    return (s == 1) ? 2.0f * w : -w;
}

extern __shared__ float _dyn_pad[];          // never touched; occupancy shaping only

__global__ __launch_bounds__(NTHR, 4)
void Hybrid_block_64175401337035_kernel(const float* __restrict__ x,
                                        float* __restrict__ y) {
    __shared__ __align__(16) float xs[NSX];
    __shared__ __align__(16) float E[NSX];   // E[p] = (-1)^p * sum_{q<p} (-1)^q xs[q]; E[0]=0
    __shared__ float warpAgg[8];

    const int tid = threadIdx.x;
    const int n = blockIdx.y;
    const int tileStart = blockIdx.x * TILE;
    const float* xg = x + (size_t)n * LSEQ;

    // ---- load input tile (zero-padded at sequence edges); dense, conflict-free ----
    #pragma unroll
    for (int q = tid; q < NSX; q += NTHR) {
        int g = tileStart - 47 + q;
        xs[q] = (q < NSV && g >= 0 && g < LSEQ) ? xg[g] : 0.0f;
    }
    __syncthreads();

    // ---- block scan of (-1)^q xs[q], chunk=5/thread; stride-5 reads are conflict-free ----
    float loc[5];
    float run = 0.0f;
    const int qb = tid * 5;
    #pragma unroll
    for (int j = 0; j < 5; ++j) {
        int q = qb + j;
        float v = 0.0f;
        if (q < NSV) { v = xs[q]; if (q & 1) v = -v; }
        run += v;
        loc[j] = run;
    }
    const unsigned lane = tid & 31;
    const unsigned wid = tid >> 5;
    float inc = run;
    #pragma unroll
    for (int o = 1; o < 32; o <<= 1) {
        float nb = __shfl_up_sync(0xffffffffu, inc, o);
        if (lane >= (unsigned)o) inc += nb;
    }
    if (lane == 31) warpAgg[wid] = inc;
    __syncthreads();
    if (tid < 8) {
        float wv = warpAgg[tid];
        #pragma unroll
        for (int o = 1; o < 8; o <<= 1) {
            float nb = __shfl_up_sync(0xffu, wv, o);
            if (tid >= o) wv += nb;
        }
        warpAgg[tid] = wv;
    }
    __syncthreads();
    float pre = inc - run;
    if (wid > 0) pre += warpAgg[wid - 1];
    if (tid == 0) E[0] = 0.0f;
    #pragma unroll
    for (int j = 0; j < 5; ++j) {
        int q = qb + j;
        if (q < NSV) {
            float v = pre + loc[j];
            // E[q+1] = (-1)^(q+1) * A[q+1]:  q even -> negative
            E[q + 1] = (q & 1) ? v : -v;
        }
    }
    __syncthreads();

    const int xl0 = tid * 4;
    const int i0 = tileStart + xl0;
    float* ybase = y + (size_t)n * NFILT * LSEQ + i0;

    // ---- 12 alternating filters: s(a) = E[a+K]-E[a]; all windows served by 9 aligned LDS.128 ----
    const float4 e16 = *(const float4*)(E + xl0 + 16);
    const float4 e32 = *(const float4*)(E + xl0 + 32);
    const float4 e40 = *(const float4*)(E + xl0 + 40);
    const float4 e44 = *(const float4*)(E + xl0 + 44);
    const float4 e48 = *(const float4*)(E + xl0 + 48);
    const float4 e52 = *(const float4*)(E + xl0 + 52);
    const float4 e56 = *(const float4*)(E + xl0 + 56);
    const float4 e64 = *(const float4*)(E + xl0 + 64);
    const float4 e80 = *(const float4*)(E + xl0 + 80);

    {
        float w0[4], w1[4];
        #define EMIT(kkidx)                                                          \
        {                                                                            \
            float4 ye, yo;                                                           \
            ye.x = fmaxf(w0[0] - w1[0], 0.0f); yo.x = fmaxf(w1[0] - w0[0], 0.0f);    \
            ye.y = fmaxf(w0[1] - w1[1], 0.0f); yo.y = fmaxf(w1[1] - w0[1], 0.0f);    \
            ye.z = fmaxf(w0[2] - w1[2], 0.0f); yo.z = fmaxf(w1[2] - w0[2], 0.0f);    \
            ye.w = fmaxf(w0[3] - w1[3], 0.0f); yo.w = fmaxf(w1[3] - w0[3], 0.0f);    \
            *(float4*)(ybase + (size_t)(kkidx) * LSEQ) = ye;                         \
            *(float4*)(ybase + (size_t)(6 + (kkidx)) * LSEQ) = yo;                   \
        }
        // K=2, o=47: W0 @47, W1 @49
        w0[0]=e44.w; w0[1]=e48.x; w0[2]=e48.y; w0[3]=e48.z;
        w1[0]=e48.y; w1[1]=e48.z; w1[2]=e48.w; w1[3]=e52.x;
        EMIT(0)
        // K=4, o=46: W0 @46, W1 @50
        w0[0]=e44.z; w0[1]=e44.w; w0[2]=e48.x; w0[3]=e48.y;
        w1[0]=e48.z; w1[1]=e48.w; w1[2]=e52.x; w1[3]=e52.y;
        EMIT(1)
        // K=8, o=44: W0 @44, W1 @52
        w0[0]=e44.x; w0[1]=e44.y; w0[2]=e44.z; w0[3]=e44.w;
        w1[0]=e52.x; w1[1]=e52.y; w1[2]=e52.z; w1[3]=e52.w;
        EMIT(2)
        // K=16, o=40: W0 @40, W1 @56
        w0[0]=e40.x; w0[1]=e40.y; w0[2]=e40.z; w0[3]=e40.w;
        w1[0]=e56.x; w1[1]=e56.y; w1[2]=e56.z; w1[3]=e56.w;
        EMIT(3)
        // K=32, o=32: W0 @32, W1 @64
        w0[0]=e32.x; w0[1]=e32.y; w0[2]=e32.z; w0[3]=e32.w;
        w1[0]=e64.x; w1[1]=e64.y; w1[2]=e64.z; w1[3]=e64.w;
        EMIT(4)
        // K=64, o=16: W0 @16, W1 @80
        w0[0]=e16.x; w0[1]=e16.y; w0[2]=e16.z; w0[3]=e16.w;
        w1[0]=e80.x; w1[1]=e80.y; w1[2]=e80.z; w1[3]=e80.w;
        EMIT(5)
        #undef EMIT
    }

    // ---- 5 quadratic filters: fully-unrolled sweep, FFMA-imm, dense LDS.128 ----
    float acc[5][4];
    #pragma unroll
    for (int t = 0; t < 5; ++t)
        #pragma unroll
        for (int pp = 0; pp < 4; ++pp) acc[t][pp] = 0.0f;

    float4 cur = *(const float4*)(xs + xl0);
    #pragma unroll
    for (int m = 0; m < 24; ++m) {
        float4 nxt = *(const float4*)(xs + xl0 + 4 * m + 4);
        float win[8] = {cur.x, cur.y, cur.z, cur.w, nxt.x, nxt.y, nxt.z, nxt.w};
        #pragma unroll
        for (int d = 0; d < 4; ++d) {
            const int c = 4 * m + d;
            #pragma unroll
            for (int t = 0; t < 5; ++t) {
                const float w = triWeightAbs(t, c);
                if (w != 0.0f) {
                    #pragma unroll
                    for (int pp = 0; pp < 4; ++pp)
                        acc[t][pp] = fmaf(w, win[d + pp], acc[t][pp]);
                }
            }
        }
        cur = nxt;
    }
    #pragma unroll
    for (int t = 0; t < 5; ++t) {
        float4 v;
        v.x = fmaxf(acc[t][0], 0.0f);
        v.y = fmaxf(acc[t][1], 0.0f);
        v.z = fmaxf(acc[t][2], 0.0f);
        v.w = fmaxf(acc[t][3], 0.0f);
        *(float4*)(ybase + (size_t)(12 + t) * LSEQ) = v;
    }
}

extern "C" void kernel_launch(void* const* d_in, const int* in_sizes, int n_in,
                              void* d_out, int out_size) {
    const float* x = (const float*)d_in[0];
    float* y = (float*)d_out;
    dim3 grid(LSEQ / TILE, NB);
    // 38KB unused dynamic smem caps occupancy at 4 blocks/SM (wave-quantization fix).
    Hybrid_block_64175401337035_kernel<<<grid, NTHR, DYN_PAD_BYTES>>>(x, y);
}

// round 5
// speedup vs baseline: 1.0467x; 1.0336x over previous
#include <cuda_runtime.h>
#include <cuda_bf16.h>

// x: (128,1,32768) fp32, W: 17 fixed filters (baked as constants), out: (128,17,32768) = relu(conv same)
// PAD_LO=47. Filters 0..5 alternating even-negative K={2,4,8,16,32,64}; 6..11 odd-negative (negation);
// 12..16 piecewise-quadratic bumps, len 1.5K for K=4..64.
//
// R5 change vs best (R2): compute identical; __launch_bounds__(256,7) -> 7 blocks/SM.
// S=148*7=1036 concurrent blocks, grid 4096 = 3.954 waves (98.8% schedule efficiency, vs 92.2%
// at 6 blocks) AND warps/SM rises 48->56. (R4 showed capping to 4 blocks loses latency coverage;
// this moves the other way.)

#define NB    128
#define LSEQ  32768
#define NFILT 17
#define TILE  1024
#define NTHR  256
#define NSV   1119          // valid xs elements = TILE + 95
#define NSX   1120

__device__ __forceinline__ float triWeightAbs(int t, int c) {
    // weight of quad filter t (t=0..4 <-> K=4,8,16,32,64) at absolute tap c (0..95); 0 outside support
    const int Ks[5] = {4, 8, 16, 32, 64};
    int K = Ks[t];
    int Lf = K + K / 2;
    int o = 47 - (Lf - 1) / 2;
    int j = c - o;
    if (j < 0 || j >= Lf) return 0.0f;
    int q = K / 4, half = K / 2;
    int s = j / half;
    int u = j - s * half;
    int num = (u < q) ? (u + 1) : (half - u);
    float b = (float)num / (float)q;        // exact: power-of-two denominator
    float w = b * b;
    return (s == 1) ? 2.0f * w : -w;
}

__global__ __launch_bounds__(NTHR, 7)
void Hybrid_block_64175401337035_kernel(const float* __restrict__ x,
                                        float* __restrict__ y) {
    __shared__ __align__(16) float xs[NSX];
    __shared__ __align__(16) float E[NSX];   // E[p] = (-1)^p * sum_{q<p} (-1)^q xs[q]; E[0]=0
    __shared__ float warpAgg[8];

    const int tid = threadIdx.x;
    const int n = blockIdx.y;
    const int tileStart = blockIdx.x * TILE;
    const float* xg = x + (size_t)n * LSEQ;

    // ---- load input tile (zero-padded at sequence edges); dense, conflict-free ----
    #pragma unroll
    for (int q = tid; q < NSX; q += NTHR) {
        int g = tileStart - 47 + q;
        xs[q] = (q < NSV && g >= 0 && g < LSEQ) ? xg[g] : 0.0f;
    }
    __syncthreads();

    // ---- block scan of (-1)^q xs[q], chunk=5/thread; stride-5 reads are conflict-free ----
    float loc[5];
    float run = 0.0f;
    const int qb = tid * 5;
    #pragma unroll
    for (int j = 0; j < 5; ++j) {
        int q = qb + j;
        float v = 0.0f;
        if (q < NSV) { v = xs[q]; if (q & 1) v = -v; }
        run += v;
        loc[j] = run;
    }
    const unsigned lane = tid & 31;
    const unsigned wid = tid >> 5;
    float inc = run;
    #pragma unroll
    for (int o = 1; o < 32; o <<= 1) {
        float nb = __shfl_up_sync(0xffffffffu, inc, o);
        if (lane >= (unsigned)o) inc += nb;
    }
    if (lane == 31) warpAgg[wid] = inc;
    __syncthreads();
    if (tid < 8) {
        float wv = warpAgg[tid];
        #pragma unroll
        for (int o = 1; o < 8; o <<= 1) {
            float nb = __shfl_up_sync(0xffu, wv, o);
            if (tid >= o) wv += nb;
        }
        warpAgg[tid] = wv;
    }
    __syncthreads();
    float pre = inc - run;
    if (wid > 0) pre += warpAgg[wid - 1];
    if (tid == 0) E[0] = 0.0f;
    #pragma unroll
    for (int j = 0; j < 5; ++j) {
        int q = qb + j;
        if (q < NSV) {
            float v = pre + loc[j];
            // E[q+1] = (-1)^(q+1) * A[q+1]:  q even -> negative
            E[q + 1] = (q & 1) ? v : -v;
        }
    }
    __syncthreads();

    const int xl0 = tid * 4;
    const int i0 = tileStart + xl0;
    float* ybase = y + (size_t)n * NFILT * LSEQ + i0;

    // ---- 12 alternating filters: s(a) = E[a+K]-E[a]; all windows served by 9 aligned LDS.128 ----
    const float4 e16 = *(const float4*)(E + xl0 + 16);
    const float4 e32 = *(const float4*)(E + xl0 + 32);
    const float4 e40 = *(const float4*)(E + xl0 + 40);
    const float4 e44 = *(const float4*)(E + xl0 + 44);
    const float4 e48 = *(const float4*)(E + xl0 + 48);
    const float4 e52 = *(const float4*)(E + xl0 + 52);
    const float4 e56 = *(const float4*)(E + xl0 + 56);
    const float4 e64 = *(const float4*)(E + xl0 + 64);
    const float4 e80 = *(const float4*)(E + xl0 + 80);

    {
        float w0[4], w1[4];
        #define EMIT(kkidx)                                                          \
        {                                                                            \
            float4 ye, yo;                                                           \
            ye.x = fmaxf(w0[0] - w1[0], 0.0f); yo.x = fmaxf(w1[0] - w0[0], 0.0f);    \
            ye.y = fmaxf(w0[1] - w1[1], 0.0f); yo.y = fmaxf(w1[1] - w0[1], 0.0f);    \
            ye.z = fmaxf(w0[2] - w1[2], 0.0f); yo.z = fmaxf(w1[2] - w0[2], 0.0f);    \
            ye.w = fmaxf(w0[3] - w1[3], 0.0f); yo.w = fmaxf(w1[3] - w0[3], 0.0f);    \
            *(float4*)(ybase + (size_t)(kkidx) * LSEQ) = ye;                         \
            *(float4*)(ybase + (size_t)(6 + (kkidx)) * LSEQ) = yo;                   \
        }
        // K=2, o=47: W0 @47, W1 @49
        w0[0]=e44.w; w0[1]=e48.x; w0[2]=e48.y; w0[3]=e48.z;
        w1[0]=e48.y; w1[1]=e48.z; w1[2]=e48.w; w1[3]=e52.x;
        EMIT(0)
        // K=4, o=46: W0 @46, W1 @50
        w0[0]=e44.z; w0[1]=e44.w; w0[2]=e48.x; w0[3]=e48.y;
        w1[0]=e48.z; w1[1]=e48.w; w1[2]=e52.x; w1[3]=e52.y;
        EMIT(1)
        // K=8, o=44: W0 @44, W1 @52
        w0[0]=e44.x; w0[1]=e44.y; w0[2]=e44.z; w0[3]=e44.w;
        w1[0]=e52.x; w1[1]=e52.y; w1[2]=e52.z; w1[3]=e52.w;
        EMIT(2)
        // K=16, o=40: W0 @40, W1 @56
        w0[0]=e40.x; w0[1]=e40.y; w0[2]=e40.z; w0[3]=e40.w;
        w1[0]=e56.x; w1[1]=e56.y; w1[2]=e56.z; w1[3]=e56.w;
        EMIT(3)
        // K=32, o=32: W0 @32, W1 @64
        w0[0]=e32.x; w0[1]=e32.y; w0[2]=e32.z; w0[3]=e32.w;
        w1[0]=e64.x; w1[1]=e64.y; w1[2]=e64.z; w1[3]=e64.w;
        EMIT(4)
        // K=64, o=16: W0 @16, W1 @80
        w0[0]=e16.x; w0[1]=e16.y; w0[2]=e16.z; w0[3]=e16.w;
        w1[0]=e80.x; w1[1]=e80.y; w1[2]=e80.z; w1[3]=e80.w;
        EMIT(5)
        #undef EMIT
    }

    // ---- 5 quadratic filters: fully-unrolled sweep, FFMA-imm, dense LDS.128 ----
    float acc[5][4];
    #pragma unroll
    for (int t = 0; t < 5; ++t)
        #pragma unroll
        for (int pp = 0; pp < 4; ++pp) acc[t][pp] = 0.0f;

    float4 cur = *(const float4*)(xs + xl0);
    #pragma unroll
    for (int m = 0; m < 24; ++m) {
        float4 nxt = *(const float4*)(xs + xl0 + 4 * m + 4);
        float win[8] = {cur.x, cur.y, cur.z, cur.w, nxt.x, nxt.y, nxt.z, nxt.w};
        #pragma unroll
        for (int d = 0; d < 4; ++d) {
            const int c = 4 * m + d;
            #pragma unroll
            for (int t = 0; t < 5; ++t) {
                const float w = triWeightAbs(t, c);
                if (w != 0.0f) {
                    #pragma unroll
                    for (int pp = 0; pp < 4; ++pp)
                        acc[t][pp] = fmaf(w, win[d + pp], acc[t][pp]);
                }
            }
        }
        cur = nxt;
    }
    #pragma unroll
    for (int t = 0; t < 5; ++t) {
        float4 v;
        v.x = fmaxf(acc[t][0], 0.0f);
        v.y = fmaxf(acc[t][1], 0.0f);
        v.z = fmaxf(acc[t][2], 0.0f);
        v.w = fmaxf(acc[t][3], 0.0f);
        *(float4*)(ybase + (size_t)(12 + t) * LSEQ) = v;
    }
}

extern "C" void kernel_launch(void* const* d_in, const int* in_sizes, int n_in,
                              void* d_out, int out_size) {
    const float* x = (const float*)d_in[0];
    float* y = (float*)d_out;
    dim3 grid(LSEQ / TILE, NB);
    Hybrid_block_64175401337035_kernel<<<grid, NTHR>>>(x, y);
}